// round 3
// baseline (speedup 1.0000x reference)
#include <cuda_runtime.h>
#include <math.h>
#include <stdint.h>

// Problem constants
#define BB 2
#define SS 2048
#define CC 1024
#define HH 16
#define DD 64
#define NROW (BB*SS)          // 4096

// -------- scratch (allocation-free: __device__ globals) --------
__device__ float g_qh[(size_t)BB*HH*SS*DD];   // [B,H,S,D]
__device__ float g_kh[(size_t)BB*HH*SS*DD];
__device__ float g_vh[(size_t)BB*HH*SS*DD];
__device__ float g_ot[(size_t)BB*SS*CC];      // attention output, [B,S,C]

// ============================================================
// Projection GEMM: out[4096,1024] = X[4096,1024] @ W[1024,1024] + bias
// permute=1: write to [B,H,S,D] head-major layout instead of row-major.
// Tile 128x128, BK=16, 256 threads, 8x8 per thread (split 4+4 mapping).
// ============================================================
__global__ __launch_bounds__(256)
void proj_kernel(const float* __restrict__ X, const float* __restrict__ W,
                 const float* __restrict__ bias, float* __restrict__ out,
                 int permute)
{
    __shared__ float As[16][128];   // transposed: As[k][m]
    __shared__ float Bs[16][128];   // Bs[k][n]

    const int tid = threadIdx.x;
    const int tx  = tid & 15;
    const int ty  = tid >> 4;
    const int mBase = blockIdx.y * 128;
    const int nBase = blockIdx.x * 128;

    float acc[8][8];
#pragma unroll
    for (int i = 0; i < 8; i++)
#pragma unroll
        for (int j = 0; j < 8; j++) acc[i][j] = 0.0f;

    for (int kt = 0; kt < CC; kt += 16) {
        // Load A tile (128x16), store transposed
#pragma unroll
        for (int i = 0; i < 2; i++) {
            int f  = tid + i * 256;          // 0..511
            int r  = f >> 2;                 // 0..127
            int c4 = f & 3;                  // 0..3
            float4 v = *(const float4*)(X + (size_t)(mBase + r) * CC + kt + c4 * 4);
            As[c4*4+0][r] = v.x;
            As[c4*4+1][r] = v.y;
            As[c4*4+2][r] = v.z;
            As[c4*4+3][r] = v.w;
        }
        // Load B tile (16x128) direct
#pragma unroll
        for (int i = 0; i < 2; i++) {
            int f  = tid + i * 256;
            int r  = f >> 5;                 // 0..15
            int c4 = f & 31;                 // 0..31
            *(float4*)&Bs[r][c4*4] =
                *(const float4*)(W + (size_t)(kt + r) * CC + nBase + c4 * 4);
        }
        __syncthreads();

#pragma unroll 8
        for (int k = 0; k < 16; k++) {
            float a[8], bv[8];
            *(float4*)&a[0]  = *(float4*)&As[k][ty*4];
            *(float4*)&a[4]  = *(float4*)&As[k][64 + ty*4];
            *(float4*)&bv[0] = *(float4*)&Bs[k][tx*4];
            *(float4*)&bv[4] = *(float4*)&Bs[k][64 + tx*4];
#pragma unroll
            for (int i = 0; i < 8; i++)
#pragma unroll
                for (int j = 0; j < 8; j++)
                    acc[i][j] = fmaf(a[i], bv[j], acc[i][j]);
        }
        __syncthreads();
    }

    // Epilogue: bias + store
#pragma unroll
    for (int i = 0; i < 8; i++) {
        int r = mBase + ((i < 4) ? (ty*4 + i) : (64 + ty*4 + (i - 4)));
#pragma unroll
        for (int jg = 0; jg < 2; jg++) {
            int c = nBase + jg*64 + tx*4;
            float4 v;
            v.x = acc[i][jg*4+0] + bias[c+0];
            v.y = acc[i][jg*4+1] + bias[c+1];
            v.z = acc[i][jg*4+2] + bias[c+2];
            v.w = acc[i][jg*4+3] + bias[c+3];
            if (permute) {
                int bb = r / SS, s = r % SS;
                int h  = c >> 6, d = c & 63;   // c..c+3 stay inside head
                *(float4*)(out + ((size_t)(bb*HH + h) * SS + s) * DD + d) = v;
            } else {
                *(float4*)(out + (size_t)r * CC + c) = v;
            }
        }
    }
}

// ============================================================
// Fused attention per (b,h, q-tile of 128 rows).
// Pass 1: scores = scale * Q@K^T, tile by tile; write raw scaled scores to
//         attn output buffer; maintain per-row online max m and sum l.
// Pass 2: re-read own scores, p = exp(s-m)/l, overwrite attn with p,
//         accumulate O = P@V from smem.
// Thread map: 256 thr as 16x16; rows r in {4ty..4ty+3, 64+4ty..}, cols split.
// ============================================================
#define SMEM_FLOATS 25088   // max(Qs 128*68 + Ks 128*65, Ps 128*132 + Vs 128*64)

__global__ __launch_bounds__(256)
void attn_kernel(float* __restrict__ attn, float* __restrict__ o_tmp)
{
    extern __shared__ float sm[];
    const int tid = threadIdx.x;
    const int tx  = tid & 15;
    const int ty  = tid >> 4;
    const int qt  = blockIdx.x;       // 0..15
    const int bh  = blockIdx.y;       // 0..31
    const int qBase = qt * 128;

    const float* Qg = g_qh + (size_t)bh * SS * DD;
    const float* Kg = g_kh + (size_t)bh * SS * DD;
    const float* Vg = g_vh + (size_t)bh * SS * DD;
    float* attn_bh  = attn + (size_t)bh * SS * SS;

    int rmap[8];
#pragma unroll
    for (int i = 0; i < 8; i++)
        rmap[i] = (i < 4) ? (ty*4 + i) : (64 + ty*4 + (i - 4));

    // ---------------- Pass 1 ----------------
    float* Qs = sm;              // [128][68]
    float* Ks = sm + 128*68;     // [128][65]

    // Load Q tile (128x64)
#pragma unroll
    for (int i = 0; i < 8; i++) {
        int f  = tid + i * 256;      // 0..2047
        int r  = f >> 4;
        int c4 = f & 15;
        float4 v = *(const float4*)(Qg + (size_t)(qBase + r) * DD + c4 * 4);
        *(float4*)&Qs[r*68 + c4*4] = v;
    }

    float m_row[8], l_row[8];
#pragma unroll
    for (int i = 0; i < 8; i++) { m_row[i] = -1e30f; l_row[i] = 0.0f; }

    const float scale = 0.125f;      // 1/sqrt(64)

    for (int kt2 = 0; kt2 < SS; kt2 += 128) {
        __syncthreads();             // Ks reuse + (first iter) Q load done
        // Load K tile -> Ks[c][k], stride 65
#pragma unroll
        for (int i = 0; i < 8; i++) {
            int f  = tid + i * 256;
            int r  = f >> 4;
            int k  = (f & 15) * 4;
            float4 v = *(const float4*)(Kg + (size_t)(kt2 + r) * DD + k);
            Ks[r*65 + k + 0] = v.x;
            Ks[r*65 + k + 1] = v.y;
            Ks[r*65 + k + 2] = v.z;
            Ks[r*65 + k + 3] = v.w;
        }
        __syncthreads();

        float acc[8][8];
#pragma unroll
        for (int i = 0; i < 8; i++)
#pragma unroll
            for (int j = 0; j < 8; j++) acc[i][j] = 0.0f;

#pragma unroll 4
        for (int k = 0; k < 64; k++) {
            float a[8], bv[8];
#pragma unroll
            for (int i = 0; i < 8; i++) a[i] = Qs[rmap[i]*68 + k];
#pragma unroll
            for (int j = 0; j < 8; j++) {
                int c = (j < 4) ? (tx*4 + j) : (64 + tx*4 + (j - 4));
                bv[j] = Ks[c*65 + k];
            }
#pragma unroll
            for (int i = 0; i < 8; i++)
#pragma unroll
                for (int j = 0; j < 8; j++)
                    acc[i][j] = fmaf(a[i], bv[j], acc[i][j]);
        }

        // scale, online softmax stats, write raw scaled scores
#pragma unroll
        for (int i = 0; i < 8; i++) {
#pragma unroll
            for (int j = 0; j < 8; j++) acc[i][j] *= scale;
            float t = acc[i][0];
#pragma unroll
            for (int j = 1; j < 8; j++) t = fmaxf(t, acc[i][j]);
#pragma unroll
            for (int off = 1; off < 16; off <<= 1)
                t = fmaxf(t, __shfl_xor_sync(0xffffffffu, t, off));
            float m_new = fmaxf(m_row[i], t);
            float psum = 0.0f;
#pragma unroll
            for (int j = 0; j < 8; j++) psum += __expf(acc[i][j] - m_new);
#pragma unroll
            for (int off = 1; off < 16; off <<= 1)
                psum += __shfl_xor_sync(0xffffffffu, psum, off);
            l_row[i] = l_row[i] * __expf(m_row[i] - m_new) + psum;
            m_row[i] = m_new;

            size_t rowoff = (size_t)(qBase + rmap[i]) * SS + kt2;
            *(float4*)&attn_bh[rowoff + tx*4] =
                make_float4(acc[i][0], acc[i][1], acc[i][2], acc[i][3]);
            *(float4*)&attn_bh[rowoff + 64 + tx*4] =
                make_float4(acc[i][4], acc[i][5], acc[i][6], acc[i][7]);
        }
    }

    float inv_l[8];
#pragma unroll
    for (int i = 0; i < 8; i++) inv_l[i] = 1.0f / l_row[i];

    // ---------------- Pass 2 ----------------
    float* Ps = sm;              // [128][132]
    float* Vs = sm + 128*132;    // [128][64]

    float acc_o[8][4];
#pragma unroll
    for (int i = 0; i < 8; i++)
#pragma unroll
        for (int j = 0; j < 4; j++) acc_o[i][j] = 0.0f;

    for (int kt2 = 0; kt2 < SS; kt2 += 128) {
        __syncthreads();             // previous tile consumed / pass1 smem done
        // Load V tile (128x64) direct
#pragma unroll
        for (int i = 0; i < 8; i++) {
            int f = tid + i * 256;
            int r = f >> 4;
            int k = (f & 15) * 4;
            *(float4*)&Vs[r*64 + k] =
                *(const float4*)(Vg + (size_t)(kt2 + r) * DD + k);
        }
        // Read back own raw scores, normalize, write p, fill Ps
#pragma unroll
        for (int i = 0; i < 8; i++) {
            int r = rmap[i];
            size_t rowoff = (size_t)(qBase + r) * SS + kt2;
#pragma unroll
            for (int jg = 0; jg < 2; jg++) {
                int c = jg*64 + tx*4;
                float4 s4 = *(float4*)&attn_bh[rowoff + c];
                float4 p4;
                p4.x = __expf(s4.x - m_row[i]) * inv_l[i];
                p4.y = __expf(s4.y - m_row[i]) * inv_l[i];
                p4.z = __expf(s4.z - m_row[i]) * inv_l[i];
                p4.w = __expf(s4.w - m_row[i]) * inv_l[i];
                *(float4*)&attn_bh[rowoff + c] = p4;
                *(float4*)&Ps[r*132 + c] = p4;
            }
        }
        __syncthreads();

        // O += P @ V   (k-chunks of 4 with float4 A loads)
#pragma unroll 4
        for (int k4 = 0; k4 < 32; k4++) {
            float a_[8][4];
#pragma unroll
            for (int i = 0; i < 8; i++)
                *(float4*)a_[i] = *(float4*)&Ps[rmap[i]*132 + k4*4];
#pragma unroll
            for (int kk = 0; kk < 4; kk++) {
                float4 bv = *(float4*)&Vs[(k4*4 + kk)*64 + tx*4];
#pragma unroll
                for (int i = 0; i < 8; i++) {
                    acc_o[i][0] = fmaf(a_[i][kk], bv.x, acc_o[i][0]);
                    acc_o[i][1] = fmaf(a_[i][kk], bv.y, acc_o[i][1]);
                    acc_o[i][2] = fmaf(a_[i][kk], bv.z, acc_o[i][2]);
                    acc_o[i][3] = fmaf(a_[i][kk], bv.w, acc_o[i][3]);
                }
            }
        }
    }

    // Write O tile to [B,S,C] scratch
    const int bb = bh / HH, h = bh % HH;
#pragma unroll
    for (int i = 0; i < 8; i++) {
        int r = qBase + rmap[i];
        float4 v = make_float4(acc_o[i][0], acc_o[i][1], acc_o[i][2], acc_o[i][3]);
        *(float4*)(o_tmp + ((size_t)(bb*SS + r)) * CC + h*DD + tx*4) = v;
    }
}

// ============================================================
extern "C" void kernel_launch(void* const* d_in, const int* in_sizes, int n_in,
                              void* d_out, int out_size)
{
    const float* q  = (const float*)d_in[0];
    const float* k  = (const float*)d_in[1];
    const float* v  = (const float*)d_in[2];
    const float* wq = (const float*)d_in[3];
    const float* bq = (const float*)d_in[4];
    const float* wk = (const float*)d_in[5];
    const float* bk = (const float*)d_in[6];
    const float* wv = (const float*)d_in[7];
    const float* bv = (const float*)d_in[8];
    const float* wo = (const float*)d_in[9];
    const float* bo = (const float*)d_in[10];

    float* out  = (float*)d_out;                          // [B,S,C]
    float* attn = out + (size_t)BB * SS * CC;             // [B,H,S,S]

    float *qh, *kh, *vh, *ot;
    cudaGetSymbolAddress((void**)&qh, g_qh);
    cudaGetSymbolAddress((void**)&kh, g_kh);
    cudaGetSymbolAddress((void**)&vh, g_vh);
    cudaGetSymbolAddress((void**)&ot, g_ot);

    dim3 pgrid(CC / 128, NROW / 128);   // (8, 32)
    proj_kernel<<<pgrid, 256>>>(q, wq, bq, qh, 1);
    proj_kernel<<<pgrid, 256>>>(k, wk, bk, kh, 1);
    proj_kernel<<<pgrid, 256>>>(v, wv, bv, vh, 1);

    size_t shmem = (size_t)SMEM_FLOATS * sizeof(float);   // 100,352 B
    cudaFuncSetAttribute(attn_kernel,
                         cudaFuncAttributeMaxDynamicSharedMemorySize,
                         (int)shmem);
    attn_kernel<<<dim3(SS / 128, BB * HH), 256, shmem>>>(attn, ot);

    proj_kernel<<<pgrid, 256>>>(ot, wo, bo, out, 0);
}

// round 5
// speedup vs baseline: 1.6190x; 1.6190x over previous
#include <cuda_runtime.h>
#include <math.h>
#include <stdint.h>

// Problem constants
#define BB 2
#define SS 2048
#define CC 1024
#define HH 16
#define DD 64
#define NROW (BB*SS)          // 4096

// -------- scratch (allocation-free: __device__ globals) --------
__device__ float g_qh[(size_t)BB*HH*SS*DD];   // [B,H,S,D]
__device__ float g_kh[(size_t)BB*HH*SS*DD];
__device__ float g_vh[(size_t)BB*HH*SS*DD];
__device__ float g_ot[(size_t)BB*SS*CC];      // attention output, [B,S,C]

// ------------ tf32 helpers ------------
__device__ __forceinline__ float tf32f(float x) {
    uint32_t u;
    asm("cvt.rna.tf32.f32 %0, %1;" : "=r"(u) : "f"(x));
    return __uint_as_float(u);
}

// D += A(16x8) * B(8x8), tf32 inputs, f32 accumulate.
__device__ __forceinline__ void mma_tf32(float4& d, const uint32_t* a, const uint32_t* b) {
    asm volatile(
        "mma.sync.aligned.m16n8k8.row.col.f32.tf32.tf32.f32 "
        "{%0,%1,%2,%3}, {%4,%5,%6,%7}, {%8,%9}, {%0,%1,%2,%3};\n"
        : "+f"(d.x), "+f"(d.y), "+f"(d.z), "+f"(d.w)
        : "r"(a[0]), "r"(a[1]), "r"(a[2]), "r"(a[3]),
          "r"(b[0]), "r"(b[1]));
}

// ============================================================
// Projection GEMM (tf32 MMA): out[4096,1024] = X @ W + bias
// Tile 128x128, BK=32. 8 warps as 2(M) x 4(N); warp tile 64x32.
// Fragment layout m16n8k8 tf32 (g = lane>>2, t = lane&3):
//   A: a0=(g,t) a1=(g+8,t) a2=(g,t+4) a3=(g+8,t+4)   [row=m, col=k]
//   B: b0=(t,g) b1=(t+4,g)                            [row=k, col=n]
//   D: d0=(g,2t) d1=(g,2t+1) d2=(g+8,2t) d3=(g+8,2t+1)
// Smem k-major with pitch 136 (stride mod 32 banks = 8 -> conflict-free).
// ============================================================
__global__ __launch_bounds__(256, 2)
void proj_kernel(const float* __restrict__ X, const float* __restrict__ W,
                 const float* __restrict__ bias, float* __restrict__ out,
                 int permute)
{
    __shared__ float As[32*136];   // As[k][m]
    __shared__ float Bs[32*136];   // Bs[k][n]

    const int tid  = threadIdx.x;
    const int lane = tid & 31;
    const int g    = lane >> 2;
    const int t    = lane & 3;
    const int w    = tid >> 5;
    const int wm   = w & 1;        // 0..1
    const int wn   = w >> 1;       // 0..3
    const int mBase = blockIdx.y * 128;
    const int nBase = blockIdx.x * 128;

    float4 acc[4][4];
#pragma unroll
    for (int i = 0; i < 4; i++)
#pragma unroll
        for (int j = 0; j < 4; j++) acc[i][j] = make_float4(0.f,0.f,0.f,0.f);

    for (int kt = 0; kt < CC; kt += 32) {
        // A tile 128x32 -> As[k][m] (transpose + tf32)
#pragma unroll
        for (int i = 0; i < 4; i++) {
            int f  = tid + i * 256;        // 0..1023
            int r  = f >> 3;               // 0..127
            int c4 = f & 7;                // 0..7
            float4 v = *(const float4*)(X + (size_t)(mBase + r) * CC + kt + c4 * 4);
            As[(c4*4+0)*136 + r] = tf32f(v.x);
            As[(c4*4+1)*136 + r] = tf32f(v.y);
            As[(c4*4+2)*136 + r] = tf32f(v.z);
            As[(c4*4+3)*136 + r] = tf32f(v.w);
        }
        // B tile 32x128 -> Bs[k][n] direct
#pragma unroll
        for (int i = 0; i < 4; i++) {
            int f = tid + i * 256;
            int r = f >> 5;                // 0..31
            int c = f & 31;                // 0..31
            float4 v = *(const float4*)(W + (size_t)(kt + r) * CC + nBase + c * 4);
            float4 cv = make_float4(tf32f(v.x), tf32f(v.y), tf32f(v.z), tf32f(v.w));
            *(float4*)&Bs[r*136 + c*4] = cv;
        }
        __syncthreads();

#pragma unroll
        for (int ks = 0; ks < 32; ks += 8) {
            uint32_t a[4][4], b[4][2];
#pragma unroll
            for (int i = 0; i < 4; i++) {
                int r0 = wm*64 + i*16 + g;
                a[i][0] = __float_as_uint(As[(ks+t  )*136 + r0    ]);
                a[i][1] = __float_as_uint(As[(ks+t  )*136 + r0 + 8]);
                a[i][2] = __float_as_uint(As[(ks+t+4)*136 + r0    ]);
                a[i][3] = __float_as_uint(As[(ks+t+4)*136 + r0 + 8]);
            }
#pragma unroll
            for (int j = 0; j < 4; j++) {
                int c = wn*32 + j*8 + g;
                b[j][0] = __float_as_uint(Bs[(ks+t  )*136 + c]);
                b[j][1] = __float_as_uint(Bs[(ks+t+4)*136 + c]);
            }
#pragma unroll
            for (int i = 0; i < 4; i++)
#pragma unroll
                for (int j = 0; j < 4; j++)
                    mma_tf32(acc[i][j], a[i], b[j]);
        }
        __syncthreads();
    }

    // Epilogue: bias + store (float2 per row-half)
#pragma unroll
    for (int i = 0; i < 4; i++) {
        int r0 = mBase + wm*64 + i*16 + g;
        int r1 = r0 + 8;
#pragma unroll
        for (int j = 0; j < 4; j++) {
            int col = nBase + wn*32 + j*8 + 2*t;
            float b0 = bias[col], b1 = bias[col+1];
            float2 v0 = make_float2(acc[i][j].x + b0, acc[i][j].y + b1);
            float2 v1 = make_float2(acc[i][j].z + b0, acc[i][j].w + b1);
            if (permute) {
                int h = col >> 6, d = col & 63;
                int bb0 = r0 / SS, s0 = r0 % SS;
                int bb1 = r1 / SS, s1 = r1 % SS;
                *(float2*)(out + ((size_t)(bb0*HH + h)*SS + s0)*DD + d) = v0;
                *(float2*)(out + ((size_t)(bb1*HH + h)*SS + s1)*DD + d) = v1;
            } else {
                *(float2*)(out + (size_t)r0 * CC + col) = v0;
                *(float2*)(out + (size_t)r1 * CC + col) = v1;
            }
        }
    }
}

// ============================================================
// Fused attention (tf32 MMA), per (b,h,q-tile=128). 256 thr = 8 warps.
// Pass 1: per s-tile (64): S = Q@K^T via MMA, track per-row running
//         (max, sumexp) in registers; cross-thread reduce once at end.
// Pass 2: recompute S per s-tile, p = exp(scale*s - m)/l, write p to
//         attn (only write!), stage p in smem as tf32, O += P@V via MMA.
// Warp layout: 2(q) x 4(s|d): warp tile 64q x 16(s or d).
// ============================================================
#define QS_OFF 0                      // Qs[d=64][q=128] pitch 136
#define KS_OFF (64*136)               // Ks[d=64][s=64]  pitch 72
#define VS_OFF (KS_OFF + 64*72)       // Vs[s=64][d=64]  pitch 72
#define PS_OFF (VS_OFF + 64*72)       // Ps[s=64][q=128] pitch 136 (also red buf)
#define SM_FLOATS (PS_OFF + 64*136)   // 26624 floats = 106496 B

__global__ __launch_bounds__(256, 2)
void attn_kernel(float* __restrict__ attn, float* __restrict__ o_tmp)
{
    extern __shared__ float sm[];
    float* Qs = sm + QS_OFF;
    float* Ks = sm + KS_OFF;
    float* Vs = sm + VS_OFF;
    float* Ps = sm + PS_OFF;

    const int tid  = threadIdx.x;
    const int lane = tid & 31;
    const int g    = lane >> 2;
    const int t    = lane & 3;
    const int w    = tid >> 5;
    const int wm   = w & 1;       // q half
    const int wn   = w >> 1;      // 0..3 (s/d quarter of 64)
    const int qt   = blockIdx.x;  // 0..15
    const int bh   = blockIdx.y;  // 0..31
    const int qBase = qt * 128;
    const float scale = 0.125f;   // 1/sqrt(64)

    const float* Qg = g_qh + (size_t)bh * SS * DD;
    const float* Kg = g_kh + (size_t)bh * SS * DD;
    const float* Vg = g_vh + (size_t)bh * SS * DD;
    float* attn_bh  = attn + (size_t)bh * SS * SS;

    // Load Q tile (128x64) -> Qs[d][q], tf32
#pragma unroll
    for (int i = 0; i < 8; i++) {
        int f  = tid + i * 256;     // 0..2047
        int r  = f >> 4;            // 0..127
        int c4 = f & 15;            // 0..15
        float4 v = *(const float4*)(Qg + (size_t)(qBase + r) * DD + c4 * 4);
        Qs[(c4*4+0)*136 + r] = tf32f(v.x);
        Qs[(c4*4+1)*136 + r] = tf32f(v.y);
        Qs[(c4*4+2)*136 + r] = tf32f(v.z);
        Qs[(c4*4+3)*136 + r] = tf32f(v.w);
    }

    float m_run[8], l_run[8];
#pragma unroll
    for (int i = 0; i < 8; i++) { m_run[i] = -1e30f; l_run[i] = 0.0f; }

    // ---------------- Pass 1: statistics only ----------------
    for (int s0 = 0; s0 < SS; s0 += 64) {
        __syncthreads();
        // K s-tile (64x64) -> Ks[d][s], tf32
#pragma unroll
        for (int i = 0; i < 4; i++) {
            int f  = tid + i * 256;   // 0..1023
            int r  = f >> 4;          // 0..63
            int c4 = f & 15;
            float4 v = *(const float4*)(Kg + (size_t)(s0 + r) * DD + c4 * 4);
            Ks[(c4*4+0)*72 + r] = tf32f(v.x);
            Ks[(c4*4+1)*72 + r] = tf32f(v.y);
            Ks[(c4*4+2)*72 + r] = tf32f(v.z);
            Ks[(c4*4+3)*72 + r] = tf32f(v.w);
        }
        __syncthreads();

        float4 accs[4][2];
#pragma unroll
        for (int i = 0; i < 4; i++)
#pragma unroll
            for (int j = 0; j < 2; j++) accs[i][j] = make_float4(0.f,0.f,0.f,0.f);

#pragma unroll
        for (int dk = 0; dk < 64; dk += 8) {
            uint32_t a[4][4], b[2][2];
#pragma unroll
            for (int i = 0; i < 4; i++) {
                int r0 = wm*64 + i*16 + g;
                a[i][0] = __float_as_uint(Qs[(dk+t  )*136 + r0    ]);
                a[i][1] = __float_as_uint(Qs[(dk+t  )*136 + r0 + 8]);
                a[i][2] = __float_as_uint(Qs[(dk+t+4)*136 + r0    ]);
                a[i][3] = __float_as_uint(Qs[(dk+t+4)*136 + r0 + 8]);
            }
#pragma unroll
            for (int j = 0; j < 2; j++) {
                int c = wn*16 + j*8 + g;
                b[j][0] = __float_as_uint(Ks[(dk+t  )*72 + c]);
                b[j][1] = __float_as_uint(Ks[(dk+t+4)*72 + c]);
            }
#pragma unroll
            for (int i = 0; i < 4; i++)
#pragma unroll
                for (int j = 0; j < 2; j++)
                    mma_tf32(accs[i][j], a[i], b[j]);
        }

        // Online per-thread stats (scaled scores)
#pragma unroll
        for (int i = 0; i < 4; i++) {
#pragma unroll
            for (int half = 0; half < 2; half++) {
                float v0, v1, v2, v3;
                if (half == 0) { v0 = accs[i][0].x; v1 = accs[i][0].y;
                                 v2 = accs[i][1].x; v3 = accs[i][1].y; }
                else           { v0 = accs[i][0].z; v1 = accs[i][0].w;
                                 v2 = accs[i][1].z; v3 = accs[i][1].w; }
                v0 *= scale; v1 *= scale; v2 *= scale; v3 *= scale;
                int ri = i*2 + half;
                float mt = fmaxf(fmaxf(v0, v1), fmaxf(v2, v3));
                float mn = fmaxf(m_run[ri], mt);
                float s = __expf(v0-mn) + __expf(v1-mn) + __expf(v2-mn) + __expf(v3-mn);
                l_run[ri] = l_run[ri] * __expf(m_run[ri] - mn) + s;
                m_run[ri] = mn;
            }
        }
    }

    // ---------------- Cross-thread reduction (16 thr/row) ----------------
    float* redm = Ps;               // [128*17]
    float* redl = Ps + 128*17;      // [128*17]
    const int slot = wn*4 + t;      // unique among the 16 threads of a row
    __syncthreads();
#pragma unroll
    for (int i = 0; i < 4; i++)
#pragma unroll
        for (int half = 0; half < 2; half++) {
            int row = wm*64 + i*16 + g + half*8;
            redm[row*17 + slot] = m_run[i*2+half];
            redl[row*17 + slot] = l_run[i*2+half];
        }
    __syncthreads();
    if (tid < 128) {
        int row = tid;
        float mf = -1e30f;
#pragma unroll
        for (int s = 0; s < 16; s++) mf = fmaxf(mf, redm[row*17 + s]);
        float lf = 0.0f;
#pragma unroll
        for (int s = 0; s < 16; s++) lf += redl[row*17 + s] * __expf(redm[row*17 + s] - mf);
        redm[row*17 + 16] = mf;
        redl[row*17 + 16] = 1.0f / lf;
    }
    __syncthreads();
    float m_fin[8], invl[8];
#pragma unroll
    for (int i = 0; i < 4; i++)
#pragma unroll
        for (int half = 0; half < 2; half++) {
            int row = wm*64 + i*16 + g + half*8;
            m_fin[i*2+half] = redm[row*17 + 16];
            invl [i*2+half] = redl[row*17 + 16];
        }

    // ---------------- Pass 2: probs + O = P@V ----------------
    float4 acc_o[4][2];
#pragma unroll
    for (int i = 0; i < 4; i++)
#pragma unroll
        for (int j = 0; j < 2; j++) acc_o[i][j] = make_float4(0.f,0.f,0.f,0.f);

    for (int s0 = 0; s0 < SS; s0 += 64) {
        __syncthreads();   // guard Ks/Vs/Ps reuse
        // K s-tile -> Ks[d][s]
#pragma unroll
        for (int i = 0; i < 4; i++) {
            int f  = tid + i * 256;
            int r  = f >> 4;
            int c4 = f & 15;
            float4 v = *(const float4*)(Kg + (size_t)(s0 + r) * DD + c4 * 4);
            Ks[(c4*4+0)*72 + r] = tf32f(v.x);
            Ks[(c4*4+1)*72 + r] = tf32f(v.y);
            Ks[(c4*4+2)*72 + r] = tf32f(v.z);
            Ks[(c4*4+3)*72 + r] = tf32f(v.w);
        }
        // V s-tile (64x64) -> Vs[s][d]
#pragma unroll
        for (int i = 0; i < 4; i++) {
            int f  = tid + i * 256;
            int r  = f >> 4;
            int c4 = f & 15;
            float4 v = *(const float4*)(Vg + (size_t)(s0 + r) * DD + c4 * 4);
            float4 cv = make_float4(tf32f(v.x), tf32f(v.y), tf32f(v.z), tf32f(v.w));
            *(float4*)&Vs[r*72 + c4*4] = cv;
        }
        __syncthreads();

        // Recompute S tile via MMA
        float4 accs[4][2];
#pragma unroll
        for (int i = 0; i < 4; i++)
#pragma unroll
            for (int j = 0; j < 2; j++) accs[i][j] = make_float4(0.f,0.f,0.f,0.f);
#pragma unroll
        for (int dk = 0; dk < 64; dk += 8) {
            uint32_t a[4][4], b[2][2];
#pragma unroll
            for (int i = 0; i < 4; i++) {
                int r0 = wm*64 + i*16 + g;
                a[i][0] = __float_as_uint(Qs[(dk+t  )*136 + r0    ]);
                a[i][1] = __float_as_uint(Qs[(dk+t  )*136 + r0 + 8]);
                a[i][2] = __float_as_uint(Qs[(dk+t+4)*136 + r0    ]);
                a[i][3] = __float_as_uint(Qs[(dk+t+4)*136 + r0 + 8]);
            }
#pragma unroll
            for (int j = 0; j < 2; j++) {
                int c = wn*16 + j*8 + g;
                b[j][0] = __float_as_uint(Ks[(dk+t  )*72 + c]);
                b[j][1] = __float_as_uint(Ks[(dk+t+4)*72 + c]);
            }
#pragma unroll
            for (int i = 0; i < 4; i++)
#pragma unroll
                for (int j = 0; j < 2; j++)
                    mma_tf32(accs[i][j], a[i], b[j]);
        }

        // p = exp(scale*s - m) * invl ; write attn ; stage tf32 p in Ps[s][q]
#pragma unroll
        for (int i = 0; i < 4; i++) {
            int row0 = wm*64 + i*16 + g;
#pragma unroll
            for (int j = 0; j < 2; j++) {
                int colL = wn*16 + j*8 + 2*t;
                float p0 = __expf(accs[i][j].x * scale - m_fin[i*2  ]) * invl[i*2  ];
                float p1 = __expf(accs[i][j].y * scale - m_fin[i*2  ]) * invl[i*2  ];
                float p2 = __expf(accs[i][j].z * scale - m_fin[i*2+1]) * invl[i*2+1];
                float p3 = __expf(accs[i][j].w * scale - m_fin[i*2+1]) * invl[i*2+1];
                *(float2*)&attn_bh[(size_t)(qBase + row0    ) * SS + s0 + colL] = make_float2(p0, p1);
                *(float2*)&attn_bh[(size_t)(qBase + row0 + 8) * SS + s0 + colL] = make_float2(p2, p3);
                Ps[(colL  )*136 + row0    ] = tf32f(p0);
                Ps[(colL+1)*136 + row0    ] = tf32f(p1);
                Ps[(colL  )*136 + row0 + 8] = tf32f(p2);
                Ps[(colL+1)*136 + row0 + 8] = tf32f(p3);
            }
        }
        __syncthreads();

        // O += P @ V
#pragma unroll
        for (int sk = 0; sk < 64; sk += 8) {
            uint32_t a[4][4], b[2][2];
#pragma unroll
            for (int i = 0; i < 4; i++) {
                int r0 = wm*64 + i*16 + g;
                a[i][0] = __float_as_uint(Ps[(sk+t  )*136 + r0    ]);
                a[i][1] = __float_as_uint(Ps[(sk+t  )*136 + r0 + 8]);
                a[i][2] = __float_as_uint(Ps[(sk+t+4)*136 + r0    ]);
                a[i][3] = __float_as_uint(Ps[(sk+t+4)*136 + r0 + 8]);
            }
#pragma unroll
            for (int j = 0; j < 2; j++) {
                int c = wn*16 + j*8 + g;
                b[j][0] = __float_as_uint(Vs[(sk+t  )*72 + c]);
                b[j][1] = __float_as_uint(Vs[(sk+t+4)*72 + c]);
            }
#pragma unroll
            for (int i = 0; i < 4; i++)
#pragma unroll
                for (int j = 0; j < 2; j++)
                    mma_tf32(acc_o[i][j], a[i], b[j]);
        }
    }

    // Epilogue: O tile -> [B,S,C] scratch
    const int bb0 = bh >> 4, h = bh & 15;
#pragma unroll
    for (int i = 0; i < 4; i++) {
        int row0 = qBase + wm*64 + i*16 + g;
#pragma unroll
        for (int j = 0; j < 2; j++) {
            int colL = wn*16 + j*8 + 2*t;
            *(float2*)(o_tmp + ((size_t)(bb0*SS + row0    )) * CC + h*64 + colL) =
                make_float2(acc_o[i][j].x, acc_o[i][j].y);
            *(float2*)(o_tmp + ((size_t)(bb0*SS + row0 + 8)) * CC + h*64 + colL) =
                make_float2(acc_o[i][j].z, acc_o[i][j].w);
        }
    }
}

// ============================================================
extern "C" void kernel_launch(void* const* d_in, const int* in_sizes, int n_in,
                              void* d_out, int out_size)
{
    const float* q  = (const float*)d_in[0];
    const float* k  = (const float*)d_in[1];
    const float* v  = (const float*)d_in[2];
    const float* wq = (const float*)d_in[3];
    const float* bq = (const float*)d_in[4];
    const float* wk = (const float*)d_in[5];
    const float* bk = (const float*)d_in[6];
    const float* wv = (const float*)d_in[7];
    const float* bv = (const float*)d_in[8];
    const float* wo = (const float*)d_in[9];
    const float* bo = (const float*)d_in[10];

    float* out  = (float*)d_out;                          // [B,S,C]
    float* attn = out + (size_t)BB * SS * CC;             // [B,H,S,S]

    float *qh, *kh, *vh, *ot;
    cudaGetSymbolAddress((void**)&qh, g_qh);
    cudaGetSymbolAddress((void**)&kh, g_kh);
    cudaGetSymbolAddress((void**)&vh, g_vh);
    cudaGetSymbolAddress((void**)&ot, g_ot);

    dim3 pgrid(CC / 128, NROW / 128);   // (8, 32)
    proj_kernel<<<pgrid, 256>>>(q, wq, bq, qh, 1);
    proj_kernel<<<pgrid, 256>>>(k, wk, bk, kh, 1);
    proj_kernel<<<pgrid, 256>>>(v, wv, bv, vh, 1);

    size_t shmem = (size_t)SM_FLOATS * sizeof(float);     // 106,496 B
    cudaFuncSetAttribute(attn_kernel,
                         cudaFuncAttributeMaxDynamicSharedMemorySize,
                         (int)shmem);
    attn_kernel<<<dim3(SS / 128, BB * HH), 256, shmem>>>(attn, ot);

    proj_kernel<<<pgrid, 256>>>(ot, wo, bo, out, 0);
}

// round 11
// speedup vs baseline: 2.3867x; 1.4742x over previous
#include <cuda_runtime.h>
#include <math.h>
#include <stdint.h>

// Problem constants
#define BB 2
#define SS 2048
#define CC 1024
#define HH 16
#define DD 64
#define NROW (BB*SS)          // 4096

// -------- scratch (allocation-free: __device__ globals) --------
__device__ float g_qh[(size_t)BB*HH*SS*DD];   // [B,H,S,D]
__device__ float g_kh[(size_t)BB*HH*SS*DD];
__device__ float g_vh[(size_t)BB*HH*SS*DD];
__device__ float g_ot[(size_t)BB*SS*CC];      // attention output, [B,S,C]

// ------------ tf32 helpers ------------
__device__ __forceinline__ float tf32f(float x) {
    uint32_t u;
    asm("cvt.rna.tf32.f32 %0, %1;" : "=r"(u) : "f"(x));
    return __uint_as_float(u);
}

// D += A(16x8) * B(8x8), tf32 inputs, f32 accumulate.
__device__ __forceinline__ void mma_tf32(float4& d, const uint32_t* a, const uint32_t* b) {
    asm volatile(
        "mma.sync.aligned.m16n8k8.row.col.f32.tf32.tf32.f32 "
        "{%0,%1,%2,%3}, {%4,%5,%6,%7}, {%8,%9}, {%0,%1,%2,%3};\n"
        : "+f"(d.x), "+f"(d.y), "+f"(d.z), "+f"(d.w)
        : "r"(a[0]), "r"(a[1]), "r"(a[2]), "r"(a[3]),
          "r"(b[0]), "r"(b[1]));
}

// ============================================================
// Projection GEMM (tf32 MMA): out[4096,1024] = X @ W + bias
// Tile 128x128, BK=32, 8 warps as 2(M) x 4(N); warp tile 64x32.
// A smem: row-major [m=128][k=32] pitch 36 (36%32==4 -> frag loads at
// banks 4g+t, conflict-free; float4 stores natural, conflict-free).
// B smem: k-major [k=32][n=128] pitch 136 (reads at 8t+8j+g, ok).
// ============================================================
__global__ __launch_bounds__(256, 2)
void proj_kernel(const float* __restrict__ X, const float* __restrict__ W,
                 const float* __restrict__ bias, float* __restrict__ out,
                 int permute)
{
    __shared__ float As[128*36];   // As[m][k]
    __shared__ float Bs[32*136];   // Bs[k][n]

    const int tid  = threadIdx.x;
    const int lane = tid & 31;
    const int g    = lane >> 2;
    const int t    = lane & 3;
    const int w    = tid >> 5;
    const int wm   = w & 1;
    const int wn   = w >> 1;
    const int mBase = blockIdx.y * 128;
    const int nBase = blockIdx.x * 128;

    float4 acc[4][4];
#pragma unroll
    for (int i = 0; i < 4; i++)
#pragma unroll
        for (int j = 0; j < 4; j++) acc[i][j] = make_float4(0.f,0.f,0.f,0.f);

    for (int kt = 0; kt < CC; kt += 32) {
        // A tile 128x32, row-major pitch 36, float4 stores
#pragma unroll
        for (int i = 0; i < 4; i++) {
            int f  = tid + i * 256;        // 0..1023
            int r  = f >> 3;               // 0..127
            int c4 = f & 7;                // 0..7
            float4 v = *(const float4*)(X + (size_t)(mBase + r) * CC + kt + c4 * 4);
            float4 cv = make_float4(tf32f(v.x), tf32f(v.y), tf32f(v.z), tf32f(v.w));
            *(float4*)&As[r*36 + c4*4] = cv;
        }
        // B tile 32x128 -> Bs[k][n]
#pragma unroll
        for (int i = 0; i < 4; i++) {
            int f = tid + i * 256;
            int r = f >> 5;                // 0..31
            int c = f & 31;                // 0..31
            float4 v = *(const float4*)(W + (size_t)(kt + r) * CC + nBase + c * 4);
            float4 cv = make_float4(tf32f(v.x), tf32f(v.y), tf32f(v.z), tf32f(v.w));
            *(float4*)&Bs[r*136 + c*4] = cv;
        }
        __syncthreads();

#pragma unroll
        for (int ks = 0; ks < 32; ks += 8) {
            uint32_t a[4][4], b[4][2];
#pragma unroll
            for (int i = 0; i < 4; i++) {
                int r0 = wm*64 + i*16 + g;
                a[i][0] = __float_as_uint(As[ r0      *36 + ks+t  ]);
                a[i][1] = __float_as_uint(As[(r0 + 8) *36 + ks+t  ]);
                a[i][2] = __float_as_uint(As[ r0      *36 + ks+t+4]);
                a[i][3] = __float_as_uint(As[(r0 + 8) *36 + ks+t+4]);
            }
#pragma unroll
            for (int j = 0; j < 4; j++) {
                int c = wn*32 + j*8 + g;
                b[j][0] = __float_as_uint(Bs[(ks+t  )*136 + c]);
                b[j][1] = __float_as_uint(Bs[(ks+t+4)*136 + c]);
            }
#pragma unroll
            for (int i = 0; i < 4; i++)
#pragma unroll
                for (int j = 0; j < 4; j++)
                    mma_tf32(acc[i][j], a[i], b[j]);
        }
        __syncthreads();
    }

    // Epilogue: bias + store
#pragma unroll
    for (int i = 0; i < 4; i++) {
        int r0 = mBase + wm*64 + i*16 + g;
        int r1 = r0 + 8;
#pragma unroll
        for (int j = 0; j < 4; j++) {
            int col = nBase + wn*32 + j*8 + 2*t;
            float b0 = bias[col], b1 = bias[col+1];
            float2 v0 = make_float2(acc[i][j].x + b0, acc[i][j].y + b1);
            float2 v1 = make_float2(acc[i][j].z + b0, acc[i][j].w + b1);
            if (permute) {
                int h = col >> 6, d = col & 63;
                int bb0 = r0 / SS, s0 = r0 % SS;
                int bb1 = r1 / SS, s1 = r1 % SS;
                *(float2*)(out + ((size_t)(bb0*HH + h)*SS + s0)*DD + d) = v0;
                *(float2*)(out + ((size_t)(bb1*HH + h)*SS + s1)*DD + d) = v1;
            } else {
                *(float2*)(out + (size_t)r0 * CC + col) = v0;
                *(float2*)(out + (size_t)r1 * CC + col) = v1;
            }
        }
    }
}

// ============================================================
// Fused attention (tf32 MMA), per (b,h,q-tile=128). 256 thr = 8 warps.
// Warp layout 4(m) x 2(n): warp tile 32q x 32(s|d)  (0.125 B/FLOP).
// Smem layouts (all conflict-free on both store and fragment-load):
//   Qs [q=128][d=64] pitch 68  (row-major; A-frag bank = 4g+t)
//   Ks [s=64][d=64]  pitch 68  (row-major; B-frag bank = 4g+t)
//   Vs [s=64][d=64]  pitch 72  (k(s)-major for PV; bank = 8t+g)
//   Ps [q=128][s=64] pitch 68  (row-major; PV A-frag bank = 4g+t)
// Pass 1: S = Q@K^T via MMA, online per-row (m,l) in regs, smem-reduce.
// Pass 2: recompute S, p = exp(scale*s - m)/l -> attn gmem (only write),
//         stage tf32 p in Ps, O += P@V.
// ============================================================
#define QS_P 68
#define KS_P 68
#define VS_P 72
#define PS_P 68
#define QS_OFF 0
#define KS_OFF (128*QS_P)
#define VS_OFF (KS_OFF + 64*KS_P)
#define PS_OFF (VS_OFF + 64*VS_P)
#define SM_FLOATS (PS_OFF + 128*PS_P)   // 26368 floats = 105,472 B

__global__ __launch_bounds__(256, 2)
void attn_kernel(float* __restrict__ attn, float* __restrict__ o_tmp)
{
    extern __shared__ float sm[];
    float* Qs = sm + QS_OFF;
    float* Ks = sm + KS_OFF;
    float* Vs = sm + VS_OFF;
    float* Ps = sm + PS_OFF;

    const int tid  = threadIdx.x;
    const int lane = tid & 31;
    const int g    = lane >> 2;
    const int t    = lane & 3;
    const int w    = tid >> 5;
    const int wm   = w & 3;       // 0..3  (q quarter: 32 rows)
    const int wn   = w >> 2;      // 0..1  (s/d half: 32 cols)
    const int qt   = blockIdx.x;  // 0..15
    const int bh   = blockIdx.y;  // 0..31
    const int qBase = qt * 128;
    const float scale = 0.125f;   // 1/sqrt(64)

    const float* Qg = g_qh + (size_t)bh * SS * DD;
    const float* Kg = g_kh + (size_t)bh * SS * DD;
    const float* Vg = g_vh + (size_t)bh * SS * DD;
    float* attn_bh  = attn + (size_t)bh * SS * SS;

    // Load Q tile (128x64) -> Qs[q][d] row-major, tf32, float4 stores
#pragma unroll
    for (int i = 0; i < 8; i++) {
        int f  = tid + i * 256;     // 0..2047
        int r  = f >> 4;            // 0..127
        int c4 = f & 15;            // 0..15
        float4 v = *(const float4*)(Qg + (size_t)(qBase + r) * DD + c4 * 4);
        float4 cv = make_float4(tf32f(v.x), tf32f(v.y), tf32f(v.z), tf32f(v.w));
        *(float4*)&Qs[r*QS_P + c4*4] = cv;
    }

    // per-thread rows: r(i,h) = wm*32 + i*16 + h*8 + g,  i,h in {0,1}
    float m_run[4], l_run[4];
#pragma unroll
    for (int i = 0; i < 4; i++) { m_run[i] = -1e30f; l_run[i] = 0.0f; }

    // ---------------- Pass 1: statistics ----------------
    for (int s0 = 0; s0 < SS; s0 += 64) {
        __syncthreads();             // prior-tile frag reads done
        // K tile (64x64) -> Ks[s][d] row-major
#pragma unroll
        for (int i = 0; i < 4; i++) {
            int f  = tid + i * 256;   // 0..1023
            int r  = f >> 4;          // 0..63
            int c4 = f & 15;
            float4 v = *(const float4*)(Kg + (size_t)(s0 + r) * DD + c4 * 4);
            float4 cv = make_float4(tf32f(v.x), tf32f(v.y), tf32f(v.z), tf32f(v.w));
            *(float4*)&Ks[r*KS_P + c4*4] = cv;
        }
        __syncthreads();

        float4 accs[2][4];
#pragma unroll
        for (int i = 0; i < 2; i++)
#pragma unroll
            for (int j = 0; j < 4; j++) accs[i][j] = make_float4(0.f,0.f,0.f,0.f);

#pragma unroll
        for (int dk = 0; dk < 64; dk += 8) {
            uint32_t a[2][4], b[4][2];
#pragma unroll
            for (int i = 0; i < 2; i++) {
                int r0 = wm*32 + i*16 + g;
                a[i][0] = __float_as_uint(Qs[ r0     *QS_P + dk+t  ]);
                a[i][1] = __float_as_uint(Qs[(r0 + 8)*QS_P + dk+t  ]);
                a[i][2] = __float_as_uint(Qs[ r0     *QS_P + dk+t+4]);
                a[i][3] = __float_as_uint(Qs[(r0 + 8)*QS_P + dk+t+4]);
            }
#pragma unroll
            for (int j = 0; j < 4; j++) {
                int c = wn*32 + j*8 + g;   // s column
                b[j][0] = __float_as_uint(Ks[c*KS_P + dk+t  ]);
                b[j][1] = __float_as_uint(Ks[c*KS_P + dk+t+4]);
            }
#pragma unroll
            for (int i = 0; i < 2; i++)
#pragma unroll
                for (int j = 0; j < 4; j++)
                    mma_tf32(accs[i][j], a[i], b[j]);
        }

        // online per-thread stats over this thread's 4 rows x 8 cols
#pragma unroll
        for (int i = 0; i < 2; i++)
#pragma unroll
            for (int h = 0; h < 2; h++) {
                float v[8];
#pragma unroll
                for (int j = 0; j < 4; j++) {
                    v[2*j]   = (h ? accs[i][j].z : accs[i][j].x) * scale;
                    v[2*j+1] = (h ? accs[i][j].w : accs[i][j].y) * scale;
                }
                int ri = i*2 + h;
                float mt = v[0];
#pragma unroll
                for (int c = 1; c < 8; c++) mt = fmaxf(mt, v[c]);
                float mn = fmaxf(m_run[ri], mt);
                float s = 0.0f;
#pragma unroll
                for (int c = 0; c < 8; c++) s += __expf(v[c] - mn);
                l_run[ri] = l_run[ri] * __expf(m_run[ri] - mn) + s;
                m_run[ri] = mn;
            }
    }

    // ---------------- Cross-thread reduction (8 thr/row) ----------------
    float* redm = Ps;                // [128*10]
    float* redl = Ps + 128*10;       // [128*10]
    const int slot = wn*4 + t;       // 0..7 unique per row
    __syncthreads();
#pragma unroll
    for (int i = 0; i < 2; i++)
#pragma unroll
        for (int h = 0; h < 2; h++) {
            int row = wm*32 + i*16 + h*8 + g;
            redm[row*10 + slot] = m_run[i*2+h];
            redl[row*10 + slot] = l_run[i*2+h];
        }
    __syncthreads();
    if (tid < 128) {
        int row = tid;
        float mf = -1e30f;
#pragma unroll
        for (int s = 0; s < 8; s++) mf = fmaxf(mf, redm[row*10 + s]);
        float lf = 0.0f;
#pragma unroll
        for (int s = 0; s < 8; s++) lf += redl[row*10 + s] * __expf(redm[row*10 + s] - mf);
        redm[row*10 + 8] = mf;
        redl[row*10 + 8] = 1.0f / lf;
    }
    __syncthreads();
    float m_fin[4], invl[4];
#pragma unroll
    for (int i = 0; i < 2; i++)
#pragma unroll
        for (int h = 0; h < 2; h++) {
            int row = wm*32 + i*16 + h*8 + g;
            m_fin[i*2+h] = redm[row*10 + 8];
            invl [i*2+h] = redl[row*10 + 8];
        }

    // ---------------- Pass 2: probs + O = P@V ----------------
    float4 acc_o[2][4];
#pragma unroll
    for (int i = 0; i < 2; i++)
#pragma unroll
        for (int j = 0; j < 4; j++) acc_o[i][j] = make_float4(0.f,0.f,0.f,0.f);

    for (int s0 = 0; s0 < SS; s0 += 64) {
        __syncthreads();   // prior-tile Ps/Vs frag reads done (and red-buf reads)
        // K tile -> Ks[s][d]
#pragma unroll
        for (int i = 0; i < 4; i++) {
            int f  = tid + i * 256;
            int r  = f >> 4;
            int c4 = f & 15;
            float4 v = *(const float4*)(Kg + (size_t)(s0 + r) * DD + c4 * 4);
            float4 cv = make_float4(tf32f(v.x), tf32f(v.y), tf32f(v.z), tf32f(v.w));
            *(float4*)&Ks[r*KS_P + c4*4] = cv;
        }
        // V tile -> Vs[s][d] pitch 72 (k(s)-major for PV B-frags)
#pragma unroll
        for (int i = 0; i < 4; i++) {
            int f  = tid + i * 256;
            int r  = f >> 4;          // s
            int c4 = f & 15;          // d/4
            float4 v = *(const float4*)(Vg + (size_t)(s0 + r) * DD + c4 * 4);
            float4 cv = make_float4(tf32f(v.x), tf32f(v.y), tf32f(v.z), tf32f(v.w));
            *(float4*)&Vs[r*VS_P + c4*4] = cv;
        }
        __syncthreads();

        // Recompute S tile
        float4 accs[2][4];
#pragma unroll
        for (int i = 0; i < 2; i++)
#pragma unroll
            for (int j = 0; j < 4; j++) accs[i][j] = make_float4(0.f,0.f,0.f,0.f);
#pragma unroll
        for (int dk = 0; dk < 64; dk += 8) {
            uint32_t a[2][4], b[4][2];
#pragma unroll
            for (int i = 0; i < 2; i++) {
                int r0 = wm*32 + i*16 + g;
                a[i][0] = __float_as_uint(Qs[ r0     *QS_P + dk+t  ]);
                a[i][1] = __float_as_uint(Qs[(r0 + 8)*QS_P + dk+t  ]);
                a[i][2] = __float_as_uint(Qs[ r0     *QS_P + dk+t+4]);
                a[i][3] = __float_as_uint(Qs[(r0 + 8)*QS_P + dk+t+4]);
            }
#pragma unroll
            for (int j = 0; j < 4; j++) {
                int c = wn*32 + j*8 + g;
                b[j][0] = __float_as_uint(Ks[c*KS_P + dk+t  ]);
                b[j][1] = __float_as_uint(Ks[c*KS_P + dk+t+4]);
            }
#pragma unroll
            for (int i = 0; i < 2; i++)
#pragma unroll
                for (int j = 0; j < 4; j++)
                    mma_tf32(accs[i][j], a[i], b[j]);
        }

        // p = exp(scale*s - m) * invl ; write attn ; stage tf32 p in Ps[q][s]
#pragma unroll
        for (int i = 0; i < 2; i++) {
            int r0 = wm*32 + i*16 + g;
#pragma unroll
            for (int j = 0; j < 4; j++) {
                int colL = wn*32 + j*8 + 2*t;
                float p0 = __expf(accs[i][j].x * scale - m_fin[i*2  ]) * invl[i*2  ];
                float p1 = __expf(accs[i][j].y * scale - m_fin[i*2  ]) * invl[i*2  ];
                float p2 = __expf(accs[i][j].z * scale - m_fin[i*2+1]) * invl[i*2+1];
                float p3 = __expf(accs[i][j].w * scale - m_fin[i*2+1]) * invl[i*2+1];
                *(float2*)&attn_bh[(size_t)(qBase + r0    ) * SS + s0 + colL] = make_float2(p0, p1);
                *(float2*)&attn_bh[(size_t)(qBase + r0 + 8) * SS + s0 + colL] = make_float2(p2, p3);
                Ps[ r0     *PS_P + colL    ] = tf32f(p0);
                Ps[ r0     *PS_P + colL + 1] = tf32f(p1);
                Ps[(r0 + 8)*PS_P + colL    ] = tf32f(p2);
                Ps[(r0 + 8)*PS_P + colL + 1] = tf32f(p3);
            }
        }
        __syncthreads();

        // O += P @ V
#pragma unroll
        for (int sk = 0; sk < 64; sk += 8) {
            uint32_t a[2][4], b[4][2];
#pragma unroll
            for (int i = 0; i < 2; i++) {
                int r0 = wm*32 + i*16 + g;
                a[i][0] = __float_as_uint(Ps[ r0     *PS_P + sk+t  ]);
                a[i][1] = __float_as_uint(Ps[(r0 + 8)*PS_P + sk+t  ]);
                a[i][2] = __float_as_uint(Ps[ r0     *PS_P + sk+t+4]);
                a[i][3] = __float_as_uint(Ps[(r0 + 8)*PS_P + sk+t+4]);
            }
#pragma unroll
            for (int j = 0; j < 4; j++) {
                int c = wn*32 + j*8 + g;   // d column
                b[j][0] = __float_as_uint(Vs[(sk+t  )*VS_P + c]);
                b[j][1] = __float_as_uint(Vs[(sk+t+4)*VS_P + c]);
            }
#pragma unroll
            for (int i = 0; i < 2; i++)
#pragma unroll
                for (int j = 0; j < 4; j++)
                    mma_tf32(acc_o[i][j], a[i], b[j]);
        }
    }

    // Epilogue: O tile -> [B,S,C] scratch
    const int bb0 = bh >> 4, hh = bh & 15;
#pragma unroll
    for (int i = 0; i < 2; i++) {
        int r0 = qBase + wm*32 + i*16 + g;
#pragma unroll
        for (int j = 0; j < 4; j++) {
            int colL = wn*32 + j*8 + 2*t;
            *(float2*)(o_tmp + ((size_t)(bb0*SS + r0    )) * CC + hh*64 + colL) =
                make_float2(acc_o[i][j].x, acc_o[i][j].y);
            *(float2*)(o_tmp + ((size_t)(bb0*SS + r0 + 8)) * CC + hh*64 + colL) =
                make_float2(acc_o[i][j].z, acc_o[i][j].w);
        }
    }
}

// ============================================================
extern "C" void kernel_launch(void* const* d_in, const int* in_sizes, int n_in,
                              void* d_out, int out_size)
{
    const float* q  = (const float*)d_in[0];
    const float* k  = (const float*)d_in[1];
    const float* v  = (const float*)d_in[2];
    const float* wq = (const float*)d_in[3];
    const float* bq = (const float*)d_in[4];
    const float* wk = (const float*)d_in[5];
    const float* bk = (const float*)d_in[6];
    const float* wv = (const float*)d_in[7];
    const float* bv = (const float*)d_in[8];
    const float* wo = (const float*)d_in[9];
    const float* bo = (const float*)d_in[10];

    float* out  = (float*)d_out;                          // [B,S,C]
    float* attn = out + (size_t)BB * SS * CC;             // [B,H,S,S]

    float *qh, *kh, *vh, *ot;
    cudaGetSymbolAddress((void**)&qh, g_qh);
    cudaGetSymbolAddress((void**)&kh, g_kh);
    cudaGetSymbolAddress((void**)&vh, g_vh);
    cudaGetSymbolAddress((void**)&ot, g_ot);

    dim3 pgrid(CC / 128, NROW / 128);   // (8, 32)
    proj_kernel<<<pgrid, 256>>>(q, wq, bq, qh, 1);
    proj_kernel<<<pgrid, 256>>>(k, wk, bk, kh, 1);
    proj_kernel<<<pgrid, 256>>>(v, wv, bv, vh, 1);

    size_t shmem = (size_t)SM_FLOATS * sizeof(float);     // 105,472 B
    cudaFuncSetAttribute(attn_kernel,
                         cudaFuncAttributeMaxDynamicSharedMemorySize,
                         (int)shmem);
    attn_kernel<<<dim3(SS / 128, BB * HH), 256, shmem>>>(attn, ot);

    proj_kernel<<<pgrid, 256>>>(ot, wo, bo, out, 0);
}